// round 7
// baseline (speedup 1.0000x reference)
#include <cuda_runtime.h>
#include <cuda_bf16.h>

// Problem: B=8, T=128, D=256
//   E[p][q]   = exp(dec[b,p] * enc[b,t,q])
//   colsum[q] = sum_p E[p][q],  rowsum[p] = sum_q E[p][q]
//   out[b,q]  = sum_t enc[b,t,q] * colsum[q]/rowsum[q]
//
// R5: each E computed once; 2 of 8 exps per step on the FMA pipe via a
// PACKED f32x2 deg-4 polynomial (fma.rn.f32x2 = FFMA2, rt2 doing 2 lanes);
// z-muls packed (mul.rn.f32x2); reduction adds as rt-1 imm-FFMA.
// 128-thread CTAs (warp owns 2 column tiles) for single-wave balance.

#define B_DIM 8
#define T_DIM 128
#define D_DIM 256
#define NT 128

typedef unsigned long long u64t;

__device__ __forceinline__ float ex2f(float x) {
    float y; asm("ex2.approx.ftz.f32 %0, %1;" : "=f"(y) : "f"(x)); return y;
}
// a + b as FFMA(a, 1.0_imm, b): imm-multiplier FFMA issues at rt 1.
__device__ __forceinline__ float addi(float a, float b) {
    float r; asm("fma.rn.f32 %0, %1, 0f3F800000, %2;" : "=f"(r) : "f"(a), "f"(b)); return r;
}
__device__ __forceinline__ u64t pk2(float lo, float hi) {
    u64t r; asm("mov.b64 %0, {%1, %2};" : "=l"(r) : "f"(lo), "f"(hi)); return r;
}
__device__ __forceinline__ void upk2(u64t v, float& lo, float& hi) {
    asm("mov.b64 {%0, %1}, %2;" : "=f"(lo), "=f"(hi) : "l"(v));
}
__device__ __forceinline__ u64t mul2(u64t a, u64t b) {
    u64t r; asm("mul.rn.f32x2 %0, %1, %2;" : "=l"(r) : "l"(a), "l"(b)); return r;
}
__device__ __forceinline__ u64t add2p(u64t a, u64t b) {
    u64t r; asm("add.rn.f32x2 %0, %1, %2;" : "=l"(r) : "l"(a), "l"(b)); return r;
}
__device__ __forceinline__ u64t fma2(u64t a, u64t b, u64t c) {
    u64t r; asm("fma.rn.f32x2 %0, %1, %2, %3;" : "=l"(r) : "l"(a), "l"(b), "l"(c)); return r;
}

__global__ void zero_out_kernel(float* __restrict__ out, int n) {
    int i = blockIdx.x * blockDim.x + threadIdx.x;
    if (i < n) out[i] = 0.0f;
}

__global__ __launch_bounds__(NT) void attn_ctx_kernel(
    const float* __restrict__ dec,   // [B, D]
    const float* __restrict__ enc,   // [B, T, D]
    float* __restrict__ out)         // [B, D]
{
    const int t   = blockIdx.x;
    const int b   = blockIdx.y;
    const int tid = threadIdx.x;
    const int w   = tid >> 5;        // 0..3
    const int j   = tid & 31;

    __shared__ float sdec[D_DIM];   // dec * log2(e)
    __shared__ float senc[D_DIM];   // enc row (b,t)
    __shared__ float srow[D_DIM];   // rowsum[p]
    __shared__ float scol[D_DIM];   // colsum[q]

    const float LOG2E = 1.4426950408889634f;

    sdec[tid]      = dec[b * D_DIM + tid] * LOG2E;
    sdec[tid + NT] = dec[b * D_DIM + tid + NT] * LOG2E;
    senc[tid]      = enc[(b * T_DIM + t) * D_DIM + tid];
    senc[tid + NT] = enc[(b * T_DIM + t) * D_DIM + tid + NT];
    srow[tid] = 0.0f;
    srow[tid + NT] = 0.0f;
    __syncthreads();

    // Packed constants (deg-4 Taylor of 2^f, f in [-0.5, 0.5])
    const u64t MAGIC2  = pk2(12582912.0f, 12582912.0f);     // 2^23 + 2^22
    const u64t NEGONE2 = pk2(-1.0f, -1.0f);
    const u64t ONE2    = pk2(1.0f, 1.0f);
    const u64t C1      = pk2(0.693147181f, 0.693147181f);
    const u64t C2      = pk2(0.240226507f, 0.240226507f);
    const u64t C3      = pk2(0.0555041087f, 0.0555041087f);
    const u64t C4      = pk2(0.00961812911f, 0.00961812911f);

    // Lane j owns rows {j + 32i}; pack row operands in pairs.
    const u64t dp0 = pk2(sdec[j],       sdec[j + 32]);
    const u64t dp1 = pk2(sdec[j + 64],  sdec[j + 96]);
    const u64t dp2 = pk2(sdec[j + 128], sdec[j + 160]);
    const u64t dp3 = pk2(sdec[j + 192], sdec[j + 224]);

    float rs[8];
    #pragma unroll
    for (int i = 0; i < 8; ++i) rs[i] = 0.0f;

    const int jp1 = (j + 1) & 31;

    // Warp w owns column tiles {w, w+4}.
    for (int ct = w; ct < 8; ct += 4) {
        float x  = senc[ct * 32 + j];   // rotates each step
        float cs = 0.0f;                // add-then-rotate colsum accumulator

        for (int so = 0; so < 4; ++so) {
            #pragma unroll
            for (int si = 0; si < 8; ++si) {
                u64t xx  = pk2(x, x);
                u64t zp0 = mul2(dp0, xx);
                u64t zp1 = mul2(dp1, xx);
                u64t zp2 = mul2(dp2, xx);
                u64t zp3 = mul2(dp3, xx);
                float z0, z1, z2, z3, z4, z5;
                upk2(zp0, z0, z1); upk2(zp1, z2, z3); upk2(zp2, z4, z5);

                float e0 = ex2f(z0);
                float e1 = ex2f(z1);
                float e2 = ex2f(z2);
                float e3 = ex2f(z3);
                float e4 = ex2f(z4);
                float e5 = ex2f(z5);

                // packed polynomial 2^z for (z6, z7)
                u64t tt = add2p(zp3, MAGIC2);          // round-to-int magic
                u64t nn = fma2(MAGIC2, NEGONE2, tt);   // n = t - MAGIC (exact)
                u64t ff = fma2(nn, NEGONE2, zp3);      // f = z - n (exact)
                u64t p  = fma2(C4, ff, C3);
                p = fma2(p, ff, C2);
                p = fma2(p, ff, C1);
                p = fma2(p, ff, ONE2);
                float tlo, thi, plo, phi;
                upk2(tt, tlo, thi);
                upk2(p,  plo, phi);
                float e6 = __int_as_float(__float_as_int(plo) + (__float_as_int(tlo) << 23));
                float e7 = __int_as_float(__float_as_int(phi) + (__float_as_int(thi) << 23));

                rs[0] = addi(e0, rs[0]);
                rs[1] = addi(e1, rs[1]);
                rs[2] = addi(e2, rs[2]);
                rs[3] = addi(e3, rs[3]);
                rs[4] = addi(e4, rs[4]);
                rs[5] = addi(e5, rs[5]);
                rs[6] = addi(e6, rs[6]);
                rs[7] = addi(e7, rs[7]);

                float s01 = addi(e0, e1);
                float s23 = addi(e2, e3);
                float s45 = addi(e4, e5);
                float s67 = addi(e6, e7);
                float esum = addi(addi(s01, s23), addi(s45, s67));

                cs = __shfl_sync(0xffffffffu, addi(cs, esum), jp1);
                x  = __shfl_sync(0xffffffffu, x, jp1);
            }
        }
        // cs = complete colsum of column ct*32+j (all 256 rows).
        scol[ct * 32 + j] = cs;
    }

    // rowsum partials: this warp saw 64 of the 256 columns for each row.
    #pragma unroll
    for (int i = 0; i < 8; ++i)
        atomicAdd(&srow[j + 32 * i], rs[i]);
    __syncthreads();

    // out[b,q] += enc[q] * colsum[q] / rowsum[q]  (two q's per thread)
    atomicAdd(&out[b * D_DIM + tid],      senc[tid]      * scol[tid]      / srow[tid]);
    atomicAdd(&out[b * D_DIM + tid + NT], senc[tid + NT] * scol[tid + NT] / srow[tid + NT]);
}

extern "C" void kernel_launch(void* const* d_in, const int* in_sizes, int n_in,
                              void* d_out, int out_size) {
    const float* dec = (const float*)d_in[0];   // [8, 256]
    const float* enc = (const float*)d_in[1];   // [8, 128, 256]
    float* out = (float*)d_out;                 // [8, 256]

    zero_out_kernel<<<(out_size + 255) / 256, 256>>>(out, out_size);

    dim3 grid(T_DIM, B_DIM);
    attn_ctx_kernel<<<grid, NT>>>(dec, enc, out);
}

// round 8
// speedup vs baseline: 1.0107x; 1.0107x over previous
#include <cuda_runtime.h>
#include <cuda_bf16.h>

// Problem: B=8, T=128, D=256
//   E[p][q]   = exp(dec[b,p] * enc[b,t,q])
//   colsum[q] = sum_p E[p][q],  rowsum[p] = sum_q E[p][q]
//   out[b,q]  = sum_t enc[b,t,q] * colsum[q]/rowsum[q]
//
// R6: R4 structure (256-thr CTA, each E once, 0.25 shfl/exp), plus:
//  - packed f32x2 z-muls (4 mul2 instead of 8 FMUL)
//  - 2 of 8 exps per step on FMA pipe via packed f32x2 deg-4 polynomial
//  - reduction adds as rt-1 imm-FFMA
// Budget/step: MUFU 48 cyc (6 ex2), FMA ~40 cyc.  (R4 was 52/53.)

#define B_DIM 8
#define T_DIM 128
#define D_DIM 256

typedef unsigned long long u64t;

__device__ __forceinline__ float ex2f(float x) {
    float y; asm("ex2.approx.ftz.f32 %0, %1;" : "=f"(y) : "f"(x)); return y;
}
// a + b as FFMA(a, 1.0_imm, b): imm-multiplier FFMA issues at rt 1.
__device__ __forceinline__ float addi(float a, float b) {
    float r; asm("fma.rn.f32 %0, %1, 0f3F800000, %2;" : "=f"(r) : "f"(a), "f"(b)); return r;
}
__device__ __forceinline__ float add1i(float a) {   // a + 1.0 (imm)
    float r; asm("add.f32 %0, %1, 0f3F800000;" : "=f"(r) : "f"(a)); return r;
}
__device__ __forceinline__ u64t pk2(float lo, float hi) {
    u64t r; asm("mov.b64 %0, {%1, %2};" : "=l"(r) : "f"(lo), "f"(hi)); return r;
}
__device__ __forceinline__ void upk2(u64t v, float& lo, float& hi) {
    asm("mov.b64 {%0, %1}, %2;" : "=f"(lo), "=f"(hi) : "l"(v));
}
__device__ __forceinline__ u64t mul2(u64t a, u64t b) {
    u64t r; asm("mul.rn.f32x2 %0, %1, %2;" : "=l"(r) : "l"(a), "l"(b)); return r;
}
__device__ __forceinline__ u64t add2p(u64t a, u64t b) {
    u64t r; asm("add.rn.f32x2 %0, %1, %2;" : "=l"(r) : "l"(a), "l"(b)); return r;
}
__device__ __forceinline__ u64t fma2(u64t a, u64t b, u64t c) {
    u64t r; asm("fma.rn.f32x2 %0, %1, %2, %3;" : "=l"(r) : "l"(a), "l"(b), "l"(c)); return r;
}

__global__ void zero_out_kernel(float* __restrict__ out, int n) {
    int i = blockIdx.x * blockDim.x + threadIdx.x;
    if (i < n) out[i] = 0.0f;
}

__global__ __launch_bounds__(D_DIM, 6) void attn_ctx_kernel(
    const float* __restrict__ dec,   // [B, D]
    const float* __restrict__ enc,   // [B, T, D]
    float* __restrict__ out)         // [B, D]
{
    const int t   = blockIdx.x;
    const int b   = blockIdx.y;
    const int tid = threadIdx.x;
    const int w   = tid >> 5;
    const int j   = tid & 31;

    __shared__ float sdec[D_DIM];   // dec * log2(e)
    __shared__ float senc[D_DIM];   // enc row (b,t)
    __shared__ float srow[D_DIM];   // rowsum[p]
    __shared__ float scol[D_DIM];   // colsum[q]

    const float LOG2E = 1.4426950408889634f;

    sdec[tid] = dec[b * D_DIM + tid] * LOG2E;
    const float xq = enc[(b * T_DIM + t) * D_DIM + tid];
    senc[tid] = xq;
    srow[tid] = 0.0f;
    __syncthreads();

    // Packed constants (deg-4 Taylor of 2^f - 1, f in [-0.5, 0.5])
    const u64t MAGIC2  = pk2(12582912.0f, 12582912.0f);     // 2^23 + 2^22
    const u64t NEGONE2 = pk2(-1.0f, -1.0f);
    const u64t C1 = pk2(0.693147181f,  0.693147181f);
    const u64t C2 = pk2(0.240226507f,  0.240226507f);
    const u64t C3 = pk2(0.0555041087f, 0.0555041087f);
    const u64t C4 = pk2(0.00961812911f,0.00961812911f);

    // Lane j owns rows {j + 32i}; pack row operands in pairs.
    const u64t dp0 = pk2(sdec[j],       sdec[j + 32]);
    const u64t dp1 = pk2(sdec[j + 64],  sdec[j + 96]);
    const u64t dp2 = pk2(sdec[j + 128], sdec[j + 160]);
    const u64t dp3 = pk2(sdec[j + 192], sdec[j + 224]);

    float rs[8];
    #pragma unroll
    for (int i = 0; i < 8; ++i) rs[i] = 0.0f;

    const int jp1 = (j + 1) & 31;
    float x  = senc[w * 32 + j];    // column operand, rotates each step
    float cs = 0.0f;                // add-then-rotate colsum accumulator

    for (int so = 0; so < 4; ++so) {
        #pragma unroll
        for (int si = 0; si < 8; ++si) {
            u64t xx  = pk2(x, x);
            u64t zp0 = mul2(dp0, xx);
            u64t zp1 = mul2(dp1, xx);
            u64t zp2 = mul2(dp2, xx);
            u64t zp3 = mul2(dp3, xx);
            float z0, z1, z2, z3, z4, z5;
            upk2(zp0, z0, z1); upk2(zp1, z2, z3); upk2(zp2, z4, z5);

            // 6 exps on MUFU
            float e0 = ex2f(z0);
            float e1 = ex2f(z1);
            float e2 = ex2f(z2);
            float e3 = ex2f(z3);
            float e4 = ex2f(z4);
            float e5 = ex2f(z5);

            // packed polynomial 2^z for (z6, z7) on the FMA pipe
            u64t tt = add2p(zp3, MAGIC2);          // round-to-int magic
            u64t nn = fma2(MAGIC2, NEGONE2, tt);   // n = tt - MAGIC (exact)
            u64t ff = fma2(nn, NEGONE2, zp3);      // f = z - n (exact)
            u64t q  = fma2(C4, ff, C3);
            q = fma2(q, ff, C2);
            q = fma2(q, ff, C1);
            u64t pp = mul2(q, ff);                 // 2^f - 1
            float tlo, thi, plo, phi;
            upk2(tt, tlo, thi);
            upk2(pp, plo, phi);
            float m6 = add1i(plo);                 // 2^f
            float m7 = add1i(phi);
            float e6 = __int_as_float(__float_as_int(m6) + (__float_as_int(tlo) << 23));
            float e7 = __int_as_float(__float_as_int(m7) + (__float_as_int(thi) << 23));

            rs[0] = addi(e0, rs[0]);
            rs[1] = addi(e1, rs[1]);
            rs[2] = addi(e2, rs[2]);
            rs[3] = addi(e3, rs[3]);
            rs[4] = addi(e4, rs[4]);
            rs[5] = addi(e5, rs[5]);
            rs[6] = addi(e6, rs[6]);
            rs[7] = addi(e7, rs[7]);

            float s01 = addi(e0, e1);
            float s23 = addi(e2, e3);
            float s45 = addi(e4, e5);
            float s67 = addi(e6, e7);
            float esum = addi(addi(s01, s23), addi(s45, s67));

            cs = __shfl_sync(0xffffffffu, addi(cs, esum), jp1);  // add-then-rotate
            x  = __shfl_sync(0xffffffffu, x, jp1);               // rotate column
        }
    }

    // cs = complete colsum of column 32w+j (all 256 rows).
    scol[w * 32 + j] = cs;

    // Rowsum partials: this warp saw 32 of the 256 columns for each row.
    #pragma unroll
    for (int i = 0; i < 8; ++i)
        atomicAdd(&srow[j + 32 * i], rs[i]);   // spread addresses, cheap
    __syncthreads();

    // out[b,q] += enc[q] * colsum[q] / rowsum[q]
    atomicAdd(&out[b * D_DIM + tid], xq * scol[tid] / srow[tid]);
}

extern "C" void kernel_launch(void* const* d_in, const int* in_sizes, int n_in,
                              void* d_out, int out_size) {
    const float* dec = (const float*)d_in[0];   // [8, 256]
    const float* enc = (const float*)d_in[1];   // [8, 128, 256]
    float* out = (float*)d_out;                 // [8, 256]

    zero_out_kernel<<<(out_size + 255) / 256, 256>>>(out, out_size);

    dim3 grid(T_DIM, B_DIM);
    attn_ctx_kernel<<<grid, D_DIM>>>(dec, enc, out);
}